// round 2
// baseline (speedup 1.0000x reference)
#include <cuda_runtime.h>
#include <cuda_bf16.h>
#include <math.h>

// Problem constants
#define B_      4
#define T_      2048
#define KDIM    1024
#define HEADS   16
#define HDIM    64
#define ROWS    (B_ * T_)          // 8192
#define HALF    (KDIM / 2)         // 512

// ---------------------------------------------------------------------------
// Scratch (device globals: allocation-free per harness rules)
// ---------------------------------------------------------------------------
__device__ float g_q[ROWS * KDIM];
__device__ float g_k[ROWS * KDIM];
__device__ float g_v[ROWS * KDIM];
__device__ float g_a[ROWS * KDIM];

// ---------------------------------------------------------------------------
// GEMM: C[m][n] = sum_k A[m][k] * B[n][k]  (+ optional bias[n])
// A: [M][Kd] row-major, B: [N][Kd] row-major (i.e. C = A @ B^T)
// Tiles: 128x128x16, 256 threads, 8x8 per thread (quadrant split for LDS.128)
// ---------------------------------------------------------------------------
__global__ __launch_bounds__(256) void gemm_xt(
    const float* __restrict__ A, const float* __restrict__ B,
    const float* __restrict__ bias, float* __restrict__ C,
    int M, int N, int Kd)
{
    __shared__ float As[16][132];
    __shared__ float Bs[16][132];

    const int tid = threadIdx.x;
    const int tx = tid & 15;
    const int ty = tid >> 4;
    const int bm = blockIdx.y * 128;
    const int bn = blockIdx.x * 128;

    float acc[8][8];
#pragma unroll
    for (int i = 0; i < 8; i++)
#pragma unroll
        for (int j = 0; j < 8; j++) acc[i][j] = 0.0f;

    const int lr = tid >> 2;        // 0..63
    const int lk = (tid & 3) << 2;  // 0,4,8,12

    const float* Ap = A + (size_t)(bm + lr) * Kd + lk;
    const float* Bp = B + (size_t)(bn + lr) * Kd + lk;
    const size_t half_off = (size_t)64 * Kd;

    for (int k0 = 0; k0 < Kd; k0 += 16) {
        float4 a0 = *(const float4*)(Ap);
        float4 a1 = *(const float4*)(Ap + half_off);
        float4 b0 = *(const float4*)(Bp);
        float4 b1 = *(const float4*)(Bp + half_off);
        __syncthreads();
        As[lk + 0][lr] = a0.x; As[lk + 1][lr] = a0.y;
        As[lk + 2][lr] = a0.z; As[lk + 3][lr] = a0.w;
        As[lk + 0][64 + lr] = a1.x; As[lk + 1][64 + lr] = a1.y;
        As[lk + 2][64 + lr] = a1.z; As[lk + 3][64 + lr] = a1.w;
        Bs[lk + 0][lr] = b0.x; Bs[lk + 1][lr] = b0.y;
        Bs[lk + 2][lr] = b0.z; Bs[lk + 3][lr] = b0.w;
        Bs[lk + 0][64 + lr] = b1.x; Bs[lk + 1][64 + lr] = b1.y;
        Bs[lk + 2][64 + lr] = b1.z; Bs[lk + 3][64 + lr] = b1.w;
        __syncthreads();
#pragma unroll
        for (int kk = 0; kk < 16; kk++) {
            float4 af0 = *(const float4*)&As[kk][ty * 4];
            float4 af1 = *(const float4*)&As[kk][64 + ty * 4];
            float4 bf0 = *(const float4*)&Bs[kk][tx * 4];
            float4 bf1 = *(const float4*)&Bs[kk][64 + tx * 4];
            float a_[8] = {af0.x, af0.y, af0.z, af0.w, af1.x, af1.y, af1.z, af1.w};
            float b_[8] = {bf0.x, bf0.y, bf0.z, bf0.w, bf1.x, bf1.y, bf1.z, bf1.w};
#pragma unroll
            for (int i = 0; i < 8; i++)
#pragma unroll
                for (int j = 0; j < 8; j++)
                    acc[i][j] = fmaf(a_[i], b_[j], acc[i][j]);
        }
        Ap += 16;
        Bp += 16;
    }

#pragma unroll
    for (int i = 0; i < 8; i++) {
        int r = bm + ((i < 4) ? (ty * 4 + i) : (64 + ty * 4 + i - 4));
#pragma unroll
        for (int jh = 0; jh < 2; jh++) {
            int c = bn + (jh ? (64 + tx * 4) : (tx * 4));
            float4 v;
            v.x = acc[i][jh * 4 + 0];
            v.y = acc[i][jh * 4 + 1];
            v.z = acc[i][jh * 4 + 2];
            v.w = acc[i][jh * 4 + 3];
            if (bias) {
                v.x += bias[c + 0]; v.y += bias[c + 1];
                v.z += bias[c + 2]; v.w += bias[c + 3];
            }
            *(float4*)&C[(size_t)r * N + c] = v;
        }
    }
}

// ---------------------------------------------------------------------------
// RoPE applied in-place to Q and K over the full 1024-dim channel.
// One thread per (row, pair). idx = bt*HALF + j; pair = channels (2j, 2j+1).
// ---------------------------------------------------------------------------
__global__ void rope_kernel(float* __restrict__ Q, float* __restrict__ K, int total)
{
    int idx = blockIdx.x * blockDim.x + threadIdx.x;
    if (idx >= total) return;
    int j = idx % HALF;
    int t = (idx / HALF) % T_;
    float theta = powf(10000.0f, -(float)j / (float)HALF);
    float ang = (float)t * theta;
    float s, c;
    sincosf(ang, &s, &c);

    float2* q2 = (float2*)Q;
    float2* k2 = (float2*)K;
    float2 q = q2[idx];
    float2 k = k2[idx];
    q2[idx] = make_float2(q.x * c - q.y * s, q.x * s + q.y * c);
    k2[idx] = make_float2(k.x * c - k.y * s, k.x * s + k.y * c);
}

// ---------------------------------------------------------------------------
// Flash attention (fp32 SIMT). One CTA = (64 q-rows) x (one batch*head).
// 128 threads: thread grid 8 (row-groups) x 16 (col-groups).
// Per key-iter BN=64: S = Q K^T -> online softmax -> P through smem -> O += P V.
// Row stats reduced across the 16 lanes owning each row via shfl_xor (<=8).
// ---------------------------------------------------------------------------
#define ASTR 68   // smem row stride (floats): 16B-aligned, conflict-mitigating

__global__ __launch_bounds__(128) void attn_kernel(
    const float* __restrict__ Q, const float* __restrict__ K,
    const float* __restrict__ V, float* __restrict__ O)
{
    extern __shared__ float sm[];
    float (*Qs)[ASTR] = (float(*)[ASTR])(sm);               // Qs[d][r]
    float (*Ks)[ASTR] = (float(*)[ASTR])(sm + 64 * ASTR);   // Ks[d][c]
    float (*Vs)[ASTR] = (float(*)[ASTR])(sm + 2 * 64 * ASTR); // Vs[c][d]
    float (*Ps)[ASTR] = (float(*)[ASTR])(sm + 3 * 64 * ASTR); // Ps[c][r]

    const int tid = threadIdx.x;
    const int tcol = tid & 15;   // 16 column-groups (4 cols each)
    const int trow = tid >> 4;   // 8 row-groups
    const int qtile = blockIdx.x;       // 0..31
    const int bh = blockIdx.y;          // 0..63
    const int b = bh >> 4;
    const int h = bh & 15;
    const size_t rowbase = (size_t)b * T_;
    const int colbase = h * HDIM;

    int rI[8];
#pragma unroll
    for (int i = 0; i < 8; i++)
        rI[i] = (i < 4) ? (trow * 4 + i) : (32 + trow * 4 + i - 4);

    // Load Q tile [64 rows x 64 dims], transposed into Qs[d][r]
    {
        const int d0 = (tid & 15) * 4;
        const int r0 = tid >> 4;
#pragma unroll
        for (int p = 0; p < 8; p++) {
            int r = p * 8 + r0;
            float4 v = *(const float4*)&Q[(rowbase + qtile * 64 + r) * KDIM + colbase + d0];
            Qs[d0 + 0][r] = v.x; Qs[d0 + 1][r] = v.y;
            Qs[d0 + 2][r] = v.z; Qs[d0 + 3][r] = v.w;
        }
    }

    float m[8], l[8], o[8][4];
#pragma unroll
    for (int i = 0; i < 8; i++) {
        m[i] = -1e30f;
        l[i] = 0.0f;
#pragma unroll
        for (int j = 0; j < 4; j++) o[i][j] = 0.0f;
    }

    for (int kt = 0; kt < T_ / 64; kt++) {
        __syncthreads();  // previous iter's reads of Ks/Vs done
        // Load K tile (transposed -> Ks[d][c]) and V tile (natural -> Vs[c][d])
        {
            const int d0 = (tid & 15) * 4;
            const int r0 = tid >> 4;
#pragma unroll
            for (int p = 0; p < 8; p++) {
                int r = p * 8 + r0;
                size_t gro = (rowbase + kt * 64 + r) * KDIM + colbase + d0;
                float4 kv = *(const float4*)&K[gro];
                Ks[d0 + 0][r] = kv.x; Ks[d0 + 1][r] = kv.y;
                Ks[d0 + 2][r] = kv.z; Ks[d0 + 3][r] = kv.w;
                float4 vv = *(const float4*)&V[gro];
                *(float4*)&Vs[r][d0] = vv;
            }
        }
        __syncthreads();

        // S = Q K^T for this tile: thread computes s[8 rows][4 cols]
        float s[8][4];
#pragma unroll
        for (int i = 0; i < 8; i++)
#pragma unroll
            for (int j = 0; j < 4; j++) s[i][j] = 0.0f;

#pragma unroll 4
        for (int d = 0; d < 64; d++) {
            float4 q0 = *(const float4*)&Qs[d][trow * 4];
            float4 q1 = *(const float4*)&Qs[d][32 + trow * 4];
            float4 kf = *(const float4*)&Ks[d][tcol * 4];
            float qv[8] = {q0.x, q0.y, q0.z, q0.w, q1.x, q1.y, q1.z, q1.w};
            float kv[4] = {kf.x, kf.y, kf.z, kf.w};
#pragma unroll
            for (int i = 0; i < 8; i++)
#pragma unroll
                for (int j = 0; j < 4; j++)
                    s[i][j] = fmaf(qv[i], kv[j], s[i][j]);
        }
#pragma unroll
        for (int i = 0; i < 8; i++)
#pragma unroll
            for (int j = 0; j < 4; j++) s[i][j] *= 0.125f;  // 1/sqrt(64)

        // Online softmax update; write P to smem
#pragma unroll
        for (int i = 0; i < 8; i++) {
            float mx = fmaxf(fmaxf(s[i][0], s[i][1]), fmaxf(s[i][2], s[i][3]));
#pragma unroll
            for (int off = 8; off >= 1; off >>= 1)
                mx = fmaxf(mx, __shfl_xor_sync(0xffffffffu, mx, off));
            float mnew = fmaxf(m[i], mx);
            float corr = __expf(m[i] - mnew);
            float rs = 0.0f;
#pragma unroll
            for (int j = 0; j < 4; j++) {
                float p = __expf(s[i][j] - mnew);
                Ps[tcol * 4 + j][rI[i]] = p;
                rs += p;
            }
#pragma unroll
            for (int off = 8; off >= 1; off >>= 1)
                rs += __shfl_xor_sync(0xffffffffu, rs, off);
            l[i] = l[i] * corr + rs;
#pragma unroll
            for (int j = 0; j < 4; j++) o[i][j] *= corr;
            m[i] = mnew;
        }
        __syncthreads();  // P visible to all

        // O += P V : thread accumulates o[8 rows][4 dims], dims = tcol*4..
#pragma unroll 4
        for (int c = 0; c < 64; c++) {
            float4 p0 = *(const float4*)&Ps[c][trow * 4];
            float4 p1 = *(const float4*)&Ps[c][32 + trow * 4];
            float4 vf = *(const float4*)&Vs[c][tcol * 4];
            float pv[8] = {p0.x, p0.y, p0.z, p0.w, p1.x, p1.y, p1.z, p1.w};
            float vv[4] = {vf.x, vf.y, vf.z, vf.w};
#pragma unroll
            for (int i = 0; i < 8; i++)
#pragma unroll
                for (int j = 0; j < 4; j++)
                    o[i][j] = fmaf(pv[i], vv[j], o[i][j]);
        }
    }

    // Normalize and write out (layout [b*t][h*64])
#pragma unroll
    for (int i = 0; i < 8; i++) {
        float inv = 1.0f / l[i];
        float4 w = make_float4(o[i][0] * inv, o[i][1] * inv, o[i][2] * inv, o[i][3] * inv);
        *(float4*)&O[(rowbase + qtile * 64 + rI[i]) * KDIM + colbase + tcol * 4] = w;
    }
}

// ---------------------------------------------------------------------------
// Launcher
// ---------------------------------------------------------------------------
extern "C" void kernel_launch(void* const* d_in, const int* in_sizes, int n_in,
                              void* d_out, int out_size)
{
    const float* x  = (const float*)d_in[0];
    const float* Wq = (const float*)d_in[1];
    const float* Wk = (const float*)d_in[2];
    const float* Wv = (const float*)d_in[3];
    const float* Wu = (const float*)d_in[4];
    const float* bu = (const float*)d_in[5];
    float* out = (float*)d_out;

    float *q, *k, *v, *a;
    cudaGetSymbolAddress((void**)&q, g_q);
    cudaGetSymbolAddress((void**)&k, g_k);
    cudaGetSymbolAddress((void**)&v, g_v);
    cudaGetSymbolAddress((void**)&a, g_a);

    dim3 ggrid(KDIM / 128, ROWS / 128);  // (8, 64)

    // QKV projections
    gemm_xt<<<ggrid, 256>>>(x, Wq, nullptr, q, ROWS, KDIM, KDIM);
    gemm_xt<<<ggrid, 256>>>(x, Wk, nullptr, k, ROWS, KDIM, KDIM);
    gemm_xt<<<ggrid, 256>>>(x, Wv, nullptr, v, ROWS, KDIM, KDIM);

    // RoPE on Q, K (in place)
    int total_pairs = ROWS * HALF;
    rope_kernel<<<(total_pairs + 255) / 256, 256>>>(q, k, total_pairs);

    // Attention
    int attn_smem = 4 * 64 * ASTR * (int)sizeof(float);  // 69632 B
    cudaFuncSetAttribute(attn_kernel, cudaFuncAttributeMaxDynamicSharedMemorySize, attn_smem);
    attn_kernel<<<dim3(T_ / 64, B_ * HEADS), 128, attn_smem>>>(q, k, v, a);

    // Output projection + bias
    gemm_xt<<<ggrid, 256>>>(a, Wu, bu, out, ROWS, KDIM, KDIM);
}

// round 3
// speedup vs baseline: 1.9982x; 1.9982x over previous
#include <cuda_runtime.h>
#include <cuda_bf16.h>
#include <math.h>

// Problem constants
#define B_      4
#define T_      2048
#define KDIM    1024
#define HEADS   16
#define HDIM    64
#define ROWS    (B_ * T_)          // 8192
#define HALF    (KDIM / 2)         // 512

// ---------------------------------------------------------------------------
// Scratch (device globals: allocation-free per harness rules)
// ---------------------------------------------------------------------------
__device__ float g_q[ROWS * KDIM];
__device__ float g_k[ROWS * KDIM];
__device__ float g_v[ROWS * KDIM];
__device__ float g_a[ROWS * KDIM];

// ---------------------------------------------------------------------------
// tf32 helpers
// ---------------------------------------------------------------------------
__device__ __forceinline__ unsigned f2tf(float f) {
    unsigned u;
    asm("cvt.rna.tf32.f32 %0, %1;" : "=r"(u) : "f"(f));
    return u;
}
__device__ __forceinline__ float f2tff(float f) {
    return __uint_as_float(f2tf(f));
}

// mma.sync m16n8k8 tf32: D = A*B + D
// A frag: a0=(g,t) a1=(g+8,t) a2=(g,t+4) a3=(g+8,t+4)  [g=lane>>2, t=lane&3]
// B frag: b0=(k=t,n=g) b1=(k=t+4,n=g)
// C frag: c0=(g,2t) c1=(g,2t+1) c2=(g+8,2t) c3=(g+8,2t+1)
__device__ __forceinline__ void mma_tf32(float* c, const unsigned* a, const unsigned* b) {
    asm volatile(
        "mma.sync.aligned.m16n8k8.row.col.f32.tf32.tf32.f32 "
        "{%0,%1,%2,%3}, {%4,%5,%6,%7}, {%8,%9}, {%0,%1,%2,%3};\n"
        : "+f"(c[0]), "+f"(c[1]), "+f"(c[2]), "+f"(c[3])
        : "r"(a[0]), "r"(a[1]), "r"(a[2]), "r"(a[3]), "r"(b[0]), "r"(b[1]));
}

// ---------------------------------------------------------------------------
// Tensor-core GEMM: C[m][n] = sum_k A[m][k]*B[n][k] (+bias[n])   (C = A @ B^T)
// 128x128x32 CTA tile, 256 threads = 8 warps (2m x 4n), warp tile 64x32.
// smem permuted: col(k) = (k%4)*10 + k/4   (k-chunk 32, row stride 40)
// -> fragment pair (k, k+4) is adjacent => aligned LDS.64, conflict-free.
// ---------------------------------------------------------------------------
#define GSTR 40

__global__ __launch_bounds__(256, 2) void gemm_tc(
    const float* __restrict__ A, const float* __restrict__ B,
    const float* __restrict__ bias, float* __restrict__ C,
    int M, int N, int Kd)
{
    __shared__ float As[128 * GSTR];
    __shared__ float Bs[128 * GSTR];

    const int tid  = threadIdx.x;
    const int lane = tid & 31;
    const int warp = tid >> 5;
    const int g = lane >> 2;
    const int t = lane & 3;
    const int t10 = t * 10;
    const int wm = warp >> 2;      // 0..1
    const int wn = warp & 3;       // 0..3
    const int bm = blockIdx.y * 128;
    const int bn = blockIdx.x * 128;

    float c[4][4][4];
#pragma unroll
    for (int i = 0; i < 4; i++)
#pragma unroll
        for (int j = 0; j < 4; j++)
#pragma unroll
            for (int e = 0; e < 4; e++) c[i][j][e] = 0.0f;

    const int lm = tid >> 3;       // 0..31
    const int kv = tid & 7;        // 0..7
    const float* Ap = A + (size_t)(bm + lm) * Kd + kv * 4;
    const float* Bp = B + (size_t)(bn + lm) * Kd + kv * 4;

    for (int k0 = 0; k0 < Kd; k0 += 32) {
        float4 ra[4], rb[4];
#pragma unroll
        for (int p = 0; p < 4; p++) {
            ra[p] = *(const float4*)(Ap + (size_t)(32 * p) * Kd + k0);
            rb[p] = *(const float4*)(Bp + (size_t)(32 * p) * Kd + k0);
        }
        __syncthreads();
#pragma unroll
        for (int p = 0; p < 4; p++) {
            float* as = &As[(lm + 32 * p) * GSTR + kv];
            float* bs = &Bs[(lm + 32 * p) * GSTR + kv];
            as[0]  = f2tff(ra[p].x); as[10] = f2tff(ra[p].y);
            as[20] = f2tff(ra[p].z); as[30] = f2tff(ra[p].w);
            bs[0]  = f2tff(rb[p].x); bs[10] = f2tff(rb[p].y);
            bs[20] = f2tff(rb[p].z); bs[30] = f2tff(rb[p].w);
        }
        __syncthreads();

#pragma unroll
        for (int s = 0; s < 4; s++) {
            unsigned a[4][4], b[4][2];
#pragma unroll
            for (int mt = 0; mt < 4; mt++) {
                const float* base = &As[(wm * 64 + mt * 16 + g) * GSTR + t10 + 2 * s];
                float2 lo = *(const float2*)base;
                float2 hi = *(const float2*)(base + 8 * GSTR);
                a[mt][0] = __float_as_uint(lo.x);
                a[mt][1] = __float_as_uint(hi.x);
                a[mt][2] = __float_as_uint(lo.y);
                a[mt][3] = __float_as_uint(hi.y);
            }
#pragma unroll
            for (int nt = 0; nt < 4; nt++) {
                float2 bb = *(const float2*)&Bs[(wn * 32 + nt * 8 + g) * GSTR + t10 + 2 * s];
                b[nt][0] = __float_as_uint(bb.x);
                b[nt][1] = __float_as_uint(bb.y);
            }
#pragma unroll
            for (int mt = 0; mt < 4; mt++)
#pragma unroll
                for (int nt = 0; nt < 4; nt++)
                    mma_tf32(c[mt][nt], a[mt], b[nt]);
        }
    }

    // Epilogue
#pragma unroll
    for (int mt = 0; mt < 4; mt++) {
        int row = bm + wm * 64 + mt * 16 + g;
#pragma unroll
        for (int nt = 0; nt < 4; nt++) {
            int col = bn + wn * 32 + nt * 8 + 2 * t;
            float bx = 0.0f, by = 0.0f;
            if (bias) { bx = bias[col]; by = bias[col + 1]; }
            float2 v0 = make_float2(c[mt][nt][0] + bx, c[mt][nt][1] + by);
            float2 v1 = make_float2(c[mt][nt][2] + bx, c[mt][nt][3] + by);
            *(float2*)&C[(size_t)row * N + col] = v0;
            *(float2*)&C[(size_t)(row + 8) * N + col] = v1;
        }
    }
}

// ---------------------------------------------------------------------------
// RoPE in-place on Q and K (full 1024-dim channel rotation, pairs (2j, 2j+1))
// ---------------------------------------------------------------------------
__global__ void rope_kernel(float* __restrict__ Q, float* __restrict__ K, int total)
{
    int idx = blockIdx.x * blockDim.x + threadIdx.x;
    if (idx >= total) return;
    int j = idx % HALF;
    int t = (idx / HALF) % T_;
    float theta = powf(10000.0f, -(float)j / (float)HALF);
    float ang = (float)t * theta;
    float s, c;
    sincosf(ang, &s, &c);

    float2* q2 = (float2*)Q;
    float2* k2 = (float2*)K;
    float2 q = q2[idx];
    float2 k = k2[idx];
    q2[idx] = make_float2(q.x * c - q.y * s, q.x * s + q.y * c);
    k2[idx] = make_float2(k.x * c - k.y * s, k.x * s + k.y * c);
}

// ---------------------------------------------------------------------------
// Flash attention w/ tf32 mma. CTA = 64 q-rows x (batch*head), 4 warps.
// Warp w owns q-rows [w*16, w*16+16). BN=64 keys/iter, head dim 64.
// smem permuted layout: col(k) = (k%4)*18 + k/4, row stride 72 (conflict-free
// fragment LDS.64). Ks[key][d-perm], Vs[d][key-perm], Ps[qrow][key-perm].
// Q fragments register-resident across all key iterations.
// ---------------------------------------------------------------------------
#define ASTR 72
#define AOFF (64 * ASTR)   // 4608 floats per array

__global__ __launch_bounds__(128, 3) void attn_tc(
    const float* __restrict__ Q, const float* __restrict__ K,
    const float* __restrict__ V, float* __restrict__ O)
{
    extern __shared__ float sm[];
    float* Ks = sm;
    float* Vs = sm + AOFF;
    float* Ps = sm + 2 * AOFF;

    const int tid  = threadIdx.x;
    const int lane = tid & 31;
    const int warp = tid >> 5;
    const int g = lane >> 2;
    const int t = lane & 3;
    const int t18 = t * 18;
    const int wrow = warp * 16;

    const int qtile = blockIdx.x;       // 0..31
    const int bh = blockIdx.y;          // 0..63
    const int b = bh >> 4;
    const int h = bh & 15;
    const size_t rowbase = (size_t)b * T_;
    const int colbase = h * HDIM;

    const int lkey = tid >> 1;          // 0..63 (loader row)
    const int ldb  = (tid & 1) * 32;    // loader d-base

    // ---- Stage Q tile into Ps (permuted, tf32), then lift fragments to regs
    {
        const float* src = Q + (rowbase + qtile * 64 + lkey) * KDIM + colbase + ldb;
#pragma unroll
        for (int i = 0; i < 8; i++) {
            float4 v = *(const float4*)(src + 4 * i);
            float* dst = &Ps[lkey * ASTR + (ldb >> 2) + i];
            dst[0]  = f2tff(v.x);
            dst[18] = f2tff(v.y);
            dst[36] = f2tff(v.z);
            dst[54] = f2tff(v.w);
        }
    }
    __syncthreads();

    unsigned qf[8][4];
#pragma unroll
    for (int s = 0; s < 8; s++) {
        const float* base = &Ps[(wrow + g) * ASTR + t18 + 2 * s];
        float2 lo = *(const float2*)base;
        float2 hi = *(const float2*)(base + 8 * ASTR);
        qf[s][0] = __float_as_uint(lo.x);
        qf[s][1] = __float_as_uint(hi.x);
        qf[s][2] = __float_as_uint(lo.y);
        qf[s][3] = __float_as_uint(hi.y);
    }

    float m0 = -1e30f, m1 = -1e30f, l0 = 0.0f, l1 = 0.0f;
    float o[8][4];
#pragma unroll
    for (int j = 0; j < 8; j++)
#pragma unroll
        for (int e = 0; e < 4; e++) o[j][e] = 0.0f;

    // Ps store column bases for this thread (C-layout col = 8j + 2t + e)
    const int pc0 = ((2 * t) & 3) * 18 + ((2 * t) >> 2);
    const int pc1 = ((2 * t + 1) & 3) * 18 + ((2 * t + 1) >> 2);

    for (int kt = 0; kt < T_ / 64; kt++) {
        __syncthreads();   // all warps done reading Ks/Vs/Ps of prev iter
        // ---- Load K tile (key-major, d-perm) and V tile (d-major, key-perm)
        {
            const size_t gb = (rowbase + kt * 64 + lkey) * KDIM + colbase + ldb;
#pragma unroll
            for (int i = 0; i < 8; i++) {
                float4 kvv = *(const float4*)(K + gb + 4 * i);
                float4 vvv = *(const float4*)(V + gb + 4 * i);
                float* kd = &Ks[lkey * ASTR + (ldb >> 2) + i];
                kd[0]  = f2tff(kvv.x);
                kd[18] = f2tff(kvv.y);
                kd[36] = f2tff(kvv.z);
                kd[54] = f2tff(kvv.w);
                int d = ldb + 4 * i;
                int vc = (lkey & 3) * 18 + (lkey >> 2);
                Vs[(d + 0) * ASTR + vc] = f2tff(vvv.x);
                Vs[(d + 1) * ASTR + vc] = f2tff(vvv.y);
                Vs[(d + 2) * ASTR + vc] = f2tff(vvv.z);
                Vs[(d + 3) * ASTR + vc] = f2tff(vvv.w);
            }
        }
        __syncthreads();

        // ---- S = Q K^T (warp tile 16 x 64)
        float sc[8][4];
#pragma unroll
        for (int j = 0; j < 8; j++)
#pragma unroll
            for (int e = 0; e < 4; e++) sc[j][e] = 0.0f;

#pragma unroll
        for (int s = 0; s < 8; s++) {
#pragma unroll
            for (int j = 0; j < 8; j++) {
                float2 kb = *(const float2*)&Ks[(j * 8 + g) * ASTR + t18 + 2 * s];
                unsigned bb[2] = {__float_as_uint(kb.x), __float_as_uint(kb.y)};
                mma_tf32(sc[j], qf[s], bb);
            }
        }
#pragma unroll
        for (int j = 0; j < 8; j++)
#pragma unroll
            for (int e = 0; e < 4; e++) sc[j][e] *= 0.125f;   // 1/sqrt(64)

        // ---- Online softmax (rows g, g+8 of warp tile)
        float mx0 = -1e30f, mx1 = -1e30f;
#pragma unroll
        for (int j = 0; j < 8; j++) {
            mx0 = fmaxf(mx0, fmaxf(sc[j][0], sc[j][1]));
            mx1 = fmaxf(mx1, fmaxf(sc[j][2], sc[j][3]));
        }
        mx0 = fmaxf(mx0, __shfl_xor_sync(0xffffffffu, mx0, 1));
        mx0 = fmaxf(mx0, __shfl_xor_sync(0xffffffffu, mx0, 2));
        mx1 = fmaxf(mx1, __shfl_xor_sync(0xffffffffu, mx1, 1));
        mx1 = fmaxf(mx1, __shfl_xor_sync(0xffffffffu, mx1, 2));

        float mn0 = fmaxf(m0, mx0);
        float mn1 = fmaxf(m1, mx1);
        float corr0 = __expf(m0 - mn0);
        float corr1 = __expf(m1 - mn1);

        float rs0 = 0.0f, rs1 = 0.0f;
        float* prow0 = &Ps[(wrow + g) * ASTR];
        float* prow1 = prow0 + 8 * ASTR;
#pragma unroll
        for (int j = 0; j < 8; j++) {
            // round P to tf32 BEFORE the l-sum so PV/l stay consistent
            float p00 = f2tff(__expf(sc[j][0] - mn0));
            float p01 = f2tff(__expf(sc[j][1] - mn0));
            float p10 = f2tff(__expf(sc[j][2] - mn1));
            float p11 = f2tff(__expf(sc[j][3] - mn1));
            rs0 += p00 + p01;
            rs1 += p10 + p11;
            prow0[pc0 + 2 * j] = p00;
            prow0[pc1 + 2 * j] = p01;
            prow1[pc0 + 2 * j] = p10;
            prow1[pc1 + 2 * j] = p11;
        }
        rs0 += __shfl_xor_sync(0xffffffffu, rs0, 1);
        rs0 += __shfl_xor_sync(0xffffffffu, rs0, 2);
        rs1 += __shfl_xor_sync(0xffffffffu, rs1, 1);
        rs1 += __shfl_xor_sync(0xffffffffu, rs1, 2);

        l0 = l0 * corr0 + rs0;
        l1 = l1 * corr1 + rs1;
#pragma unroll
        for (int j = 0; j < 8; j++) {
            o[j][0] *= corr0; o[j][1] *= corr0;
            o[j][2] *= corr1; o[j][3] *= corr1;
        }
        m0 = mn0; m1 = mn1;
        __syncwarp();  // Ps writes visible within warp

        // ---- O += P V (warp tile 16 x 64, k over 64 keys)
#pragma unroll
        for (int s = 0; s < 8; s++) {
            const float* pb = &Ps[(wrow + g) * ASTR + t18 + 2 * s];
            float2 plo = *(const float2*)pb;
            float2 phi = *(const float2*)(pb + 8 * ASTR);
            unsigned pa[4] = {__float_as_uint(plo.x), __float_as_uint(phi.x),
                              __float_as_uint(plo.y), __float_as_uint(phi.y)};
#pragma unroll
            for (int j = 0; j < 8; j++) {
                float2 vb = *(const float2*)&Vs[(j * 8 + g) * ASTR + t18 + 2 * s];
                unsigned bb[2] = {__float_as_uint(vb.x), __float_as_uint(vb.y)};
                mma_tf32(o[j], pa, bb);
            }
        }
    }

    // ---- Normalize and write out ([b*t][h*64])
    float inv0 = 1.0f / l0;
    float inv1 = 1.0f / l1;
    size_t orow0 = (rowbase + qtile * 64 + wrow + g) * KDIM + colbase;
    size_t orow1 = orow0 + (size_t)8 * KDIM;
#pragma unroll
    for (int j = 0; j < 8; j++) {
        int col = 8 * j + 2 * t;
        *(float2*)&O[orow0 + col] = make_float2(o[j][0] * inv0, o[j][1] * inv0);
        *(float2*)&O[orow1 + col] = make_float2(o[j][2] * inv1, o[j][3] * inv1);
    }
}

// ---------------------------------------------------------------------------
// Launcher
// ---------------------------------------------------------------------------
extern "C" void kernel_launch(void* const* d_in, const int* in_sizes, int n_in,
                              void* d_out, int out_size)
{
    const float* x  = (const float*)d_in[0];
    const float* Wq = (const float*)d_in[1];
    const float* Wk = (const float*)d_in[2];
    const float* Wv = (const float*)d_in[3];
    const float* Wu = (const float*)d_in[4];
    const float* bu = (const float*)d_in[5];
    float* out = (float*)d_out;

    float *q, *k, *v, *a;
    cudaGetSymbolAddress((void**)&q, g_q);
    cudaGetSymbolAddress((void**)&k, g_k);
    cudaGetSymbolAddress((void**)&v, g_v);
    cudaGetSymbolAddress((void**)&a, g_a);

    dim3 ggrid(KDIM / 128, ROWS / 128);  // (8, 64)

    // QKV projections (tensor core, tf32)
    gemm_tc<<<ggrid, 256>>>(x, Wq, nullptr, q, ROWS, KDIM, KDIM);
    gemm_tc<<<ggrid, 256>>>(x, Wk, nullptr, k, ROWS, KDIM, KDIM);
    gemm_tc<<<ggrid, 256>>>(x, Wv, nullptr, v, ROWS, KDIM, KDIM);

    // RoPE on Q, K (in place)
    int total_pairs = ROWS * HALF;
    rope_kernel<<<(total_pairs + 255) / 256, 256>>>(q, k, total_pairs);

    // Attention (tensor core, tf32)
    int attn_smem = 3 * AOFF * (int)sizeof(float);  // 55296 B
    cudaFuncSetAttribute(attn_tc, cudaFuncAttributeMaxDynamicSharedMemorySize, attn_smem);
    attn_tc<<<dim3(T_ / 64, B_ * HEADS), 128, attn_smem>>>(q, k, v, a);

    // Output projection + bias
    gemm_tc<<<ggrid, 256>>>(a, Wu, bu, out, ROWS, KDIM, KDIM);
}

// round 4
// speedup vs baseline: 2.1361x; 1.0690x over previous
#include <cuda_runtime.h>
#include <cuda_bf16.h>
#include <math.h>

// Problem constants
#define B_      4
#define T_      2048
#define KDIM    1024
#define HEADS   16
#define HDIM    64
#define ROWS    (B_ * T_)          // 8192
#define HALF    (KDIM / 2)         // 512

// ---------------------------------------------------------------------------
// Scratch (device globals: allocation-free per harness rules)
// ---------------------------------------------------------------------------
__device__ float g_q[ROWS * KDIM];
__device__ float g_k[ROWS * KDIM];
__device__ float g_v[ROWS * KDIM];
__device__ float g_a[ROWS * KDIM];

// ---------------------------------------------------------------------------
// Helpers: tf32 convert, mma, cp.async
// ---------------------------------------------------------------------------
__device__ __forceinline__ unsigned f2tf(float f) {
    unsigned u;
    asm("cvt.rna.tf32.f32 %0, %1;" : "=r"(u) : "f"(f));
    return u;
}
__device__ __forceinline__ float f2tff(float f) {
    return __uint_as_float(f2tf(f));
}

// mma.sync m16n8k8 tf32: D = A*B + D
// A frag: a0=(g,t) a1=(g+8,t) a2=(g,t+4) a3=(g+8,t+4)  [g=lane>>2, t=lane&3]
// B frag: b0=(k=t,n=g) b1=(k=t+4,n=g)
// C frag: c0=(g,2t) c1=(g,2t+1) c2=(g+8,2t) c3=(g+8,2t+1)
__device__ __forceinline__ void mma_tf32(float* c, const unsigned* a, const unsigned* b) {
    asm volatile(
        "mma.sync.aligned.m16n8k8.row.col.f32.tf32.tf32.f32 "
        "{%0,%1,%2,%3}, {%4,%5,%6,%7}, {%8,%9}, {%0,%1,%2,%3};\n"
        : "+f"(c[0]), "+f"(c[1]), "+f"(c[2]), "+f"(c[3])
        : "r"(a[0]), "r"(a[1]), "r"(a[2]), "r"(a[3]), "r"(b[0]), "r"(b[1]));
}

__device__ __forceinline__ void cp16(float* dst_smem, const float* src) {
    unsigned d = (unsigned)__cvta_generic_to_shared(dst_smem);
    asm volatile("cp.async.cg.shared.global [%0], [%1], 16;\n" :: "r"(d), "l"(src));
}
#define CP_COMMIT() asm volatile("cp.async.commit_group;\n" ::: "memory")
#define CP_WAIT0()  asm volatile("cp.async.wait_group 0;\n" ::: "memory")

// ---------------------------------------------------------------------------
// Tensor-core GEMM: C[m][n] = sum_k A[m][k]*B[n][k]   (C = A @ B^T)
// MODE: 0 = plain, 1 = RoPE epilogue (Q/K proj), 2 = +bias (output proj)
// 128x128x32 CTA tile, 256 threads = 8 warps (2m x 4n), warp tile 64x32.
// cp.async 2-stage pipeline; smem raw fp32 [row][k] with stride 36
// (36 mod 32 = 4 -> fragment lanes hit banks 4g+t: conflict-free).
// tf32 conversion happens at fragment-load time (cvt.rna in registers).
// ---------------------------------------------------------------------------
#define GS 36   // smem row stride (floats) for 32-wide k-chunk

template<int MODE>
__global__ __launch_bounds__(256, 2) void gemm_tc(
    const float* __restrict__ A, const float* __restrict__ B,
    const float* __restrict__ bias, float* __restrict__ C,
    int M, int N, int Kd)
{
    extern __shared__ float sm[];
    float* As = sm;                 // [2][128*GS]
    float* Bs = sm + 2 * 128 * GS;  // [2][128*GS]

    const int tid  = threadIdx.x;
    const int lane = tid & 31;
    const int warp = tid >> 5;
    const int g = lane >> 2;
    const int t = lane & 3;
    const int wm = warp >> 2;      // 0..1
    const int wn = warp & 3;       // 0..3
    const int bm = blockIdx.y * 128;
    const int bn = blockIdx.x * 128;

    float c[4][4][4];
#pragma unroll
    for (int i = 0; i < 4; i++)
#pragma unroll
        for (int j = 0; j < 4; j++)
#pragma unroll
            for (int e = 0; e < 4; e++) c[i][j][e] = 0.0f;

    // cp.async loader mapping: each thread copies 4x16B for A and B per chunk
    const int lrow = tid >> 1;          // 0..127
    const int lcb  = (tid & 1) * 16;    // float offset 0 or 16
    const float* Ap = A + (size_t)(bm + lrow) * Kd + lcb;
    const float* Bp = B + (size_t)(bn + lrow) * Kd + lcb;
    float* Asl = &As[lrow * GS + lcb];
    float* Bsl = &Bs[lrow * GS + lcb];

    // prologue: stage 0 <- k0=0
#pragma unroll
    for (int i = 0; i < 4; i++) {
        cp16(Asl + 4 * i, Ap + 4 * i);
        cp16(Bsl + 4 * i, Bp + 4 * i);
    }
    CP_COMMIT();

    const int a_base0 = (wm * 64 + g) * GS;
    const int b_base0 = (wn * 32 + g) * GS;

    for (int k0 = 0; k0 < Kd; k0 += 32) {
        const int st = (k0 >> 5) & 1;
        CP_WAIT0();
        __syncthreads();
        if (k0 + 32 < Kd) {
            const int stn = st ^ 1;
            float* Asd = Asl + stn * 128 * GS;
            float* Bsd = Bsl + stn * 128 * GS;
#pragma unroll
            for (int i = 0; i < 4; i++) {
                cp16(Asd + 4 * i, Ap + k0 + 32 + 4 * i);
                cp16(Bsd + 4 * i, Bp + k0 + 32 + 4 * i);
            }
        }
        CP_COMMIT();

        const float* Ac = As + st * 128 * GS;
        const float* Bc = Bs + st * 128 * GS;
#pragma unroll
        for (int s = 0; s < 4; s++) {
            unsigned a[4][4], b[4][2];
            const int kc = 8 * s + t;
#pragma unroll
            for (int mt = 0; mt < 4; mt++) {
                const float* p = &Ac[a_base0 + mt * 16 * GS + kc];
                a[mt][0] = f2tf(p[0]);
                a[mt][1] = f2tf(p[8 * GS]);
                a[mt][2] = f2tf(p[4]);
                a[mt][3] = f2tf(p[8 * GS + 4]);
            }
#pragma unroll
            for (int nt = 0; nt < 4; nt++) {
                const float* p = &Bc[b_base0 + nt * 8 * GS + kc];
                b[nt][0] = f2tf(p[0]);
                b[nt][1] = f2tf(p[4]);
            }
#pragma unroll
            for (int mt = 0; mt < 4; mt++)
#pragma unroll
                for (int nt = 0; nt < 4; nt++)
                    mma_tf32(c[mt][nt], a[mt], b[nt]);
        }
        __syncthreads();
    }

    // Epilogue
#pragma unroll
    for (int mt = 0; mt < 4; mt++) {
        int row = bm + wm * 64 + mt * 16 + g;
#pragma unroll
        for (int nt = 0; nt < 4; nt++) {
            int col = bn + wn * 32 + nt * 8 + 2 * t;   // even
            float v0x = c[mt][nt][0], v0y = c[mt][nt][1];
            float v1x = c[mt][nt][2], v1y = c[mt][nt][3];
            if (MODE == 1) {
                // RoPE: rotate pair (col, col+1) = pair index j = col/2
                int j = col >> 1;
                float theta = powf(10000.0f, -(float)j * (1.0f / (float)HALF));
                int t0 = row & (T_ - 1);
                float s0, c0; sincosf((float)t0 * theta, &s0, &c0);
                float s1, c1; sincosf((float)(t0 + 8) * theta, &s1, &c1);
                float r0x = v0x * c0 - v0y * s0;
                float r0y = v0x * s0 + v0y * c0;
                float r1x = v1x * c1 - v1y * s1;
                float r1y = v1x * s1 + v1y * c1;
                v0x = r0x; v0y = r0y; v1x = r1x; v1y = r1y;
            } else if (MODE == 2) {
                float bx = bias[col], by = bias[col + 1];
                v0x += bx; v0y += by; v1x += bx; v1y += by;
            }
            *(float2*)&C[(size_t)row * N + col] = make_float2(v0x, v0y);
            *(float2*)&C[(size_t)(row + 8) * N + col] = make_float2(v1x, v1y);
        }
    }
}

// ---------------------------------------------------------------------------
// Flash attention, tf32 mma, cp.async 2-stage pipeline, P via shuffles.
// CTA = 64 q-rows x (batch*head), 4 warps; warp owns q-rows [w*16, w*16+16).
// smem per stage: K[key][d] stride 68 (banks 4g+t, conflict-free),
//                 V[key][d] stride 72 (banks 8t+g, conflict-free).
// Q fragments register-resident; P redistributed C-frag -> A-frag via shfl.
// ---------------------------------------------------------------------------
#define KSTR 68
#define VSTR 72
#define SSZ  (64 * KSTR + 64 * VSTR)   // 8960 floats per stage

__global__ __launch_bounds__(128, 3) void attn_tc(
    const float* __restrict__ Q, const float* __restrict__ K,
    const float* __restrict__ V, float* __restrict__ O)
{
    extern __shared__ float sm[];

    const int tid  = threadIdx.x;
    const int lane = tid & 31;
    const int warp = tid >> 5;
    const int g = lane >> 2;
    const int t = lane & 3;
    const int wrow = warp * 16;

    const int qtile = blockIdx.x;       // 0..31
    const int bh = blockIdx.y;          // 0..63
    const int b = bh >> 4;
    const int h = bh & 15;
    const size_t rowbase = (size_t)b * T_;
    const int colbase = h * HDIM;

    // loader mapping: thread copies 8x16B per tensor per tile
    const int lrow = tid >> 1;          // 0..63
    const int lcb  = (tid & 1) * 32;    // float offset 0 or 32

    float* K0 = sm;
    float* V0 = sm + 64 * KSTR;
    float* K1 = sm + SSZ;
    float* V1 = sm + SSZ + 64 * KSTR;

    // ---- Stage Q tile (raw fp32) into V1 region via cp.async, lift frags
    {
        const float* src = Q + (rowbase + qtile * 64 + lrow) * KDIM + colbase + lcb;
        float* dst = V1 + lrow * VSTR + lcb;
#pragma unroll
        for (int i = 0; i < 8; i++) cp16(dst + 4 * i, src + 4 * i);
        CP_COMMIT();
        CP_WAIT0();
    }
    __syncthreads();

    unsigned qf[8][4];
#pragma unroll
    for (int s = 0; s < 8; s++) {
        const float* p = &V1[(wrow + g) * VSTR + 8 * s + t];
        qf[s][0] = f2tf(p[0]);
        qf[s][1] = f2tf(p[8 * VSTR]);
        qf[s][2] = f2tf(p[4]);
        qf[s][3] = f2tf(p[8 * VSTR + 4]);
    }
    __syncthreads();   // all lifts done before tile loads overwrite V1

    // ---- prologue: tile 0 -> stage 0
    {
        const size_t gb = (rowbase + lrow) * KDIM + colbase + lcb;
        float* kd = K0 + lrow * KSTR + lcb;
        float* vd = V0 + lrow * VSTR + lcb;
#pragma unroll
        for (int i = 0; i < 8; i++) {
            cp16(kd + 4 * i, K + gb + 4 * i);
            cp16(vd + 4 * i, V + gb + 4 * i);
        }
        CP_COMMIT();
    }

    float m0 = -1e30f, m1 = -1e30f, l0 = 0.0f, l1 = 0.0f;
    float o[8][4];
#pragma unroll
    for (int j = 0; j < 8; j++)
#pragma unroll
        for (int e = 0; e < 4; e++) o[j][e] = 0.0f;

    const int s0lane = 4 * g + (t >> 1);
    const int s1lane = s0lane + 2;
    const bool odd = (t & 1);

    for (int kt = 0; kt < T_ / 64; kt++) {
        const int st = kt & 1;
        float* Kc = st ? K1 : K0;
        float* Vc = st ? V1 : V0;

        CP_WAIT0();
        __syncthreads();

        if (kt + 1 < T_ / 64) {
            const size_t gb = (rowbase + (kt + 1) * 64 + lrow) * KDIM + colbase + lcb;
            float* kd = (st ? K0 : K1) + lrow * KSTR + lcb;
            float* vd = (st ? V0 : V1) + lrow * VSTR + lcb;
#pragma unroll
            for (int i = 0; i < 8; i++) {
                cp16(kd + 4 * i, K + gb + 4 * i);
                cp16(vd + 4 * i, V + gb + 4 * i);
            }
        }
        CP_COMMIT();

        // ---- S = Q K^T (warp tile 16 x 64)
        float sc[8][4];
#pragma unroll
        for (int j = 0; j < 8; j++)
#pragma unroll
            for (int e = 0; e < 4; e++) sc[j][e] = 0.0f;

#pragma unroll
        for (int s = 0; s < 8; s++) {
#pragma unroll
            for (int j = 0; j < 8; j++) {
                const float* kb = &Kc[(j * 8 + g) * KSTR + 8 * s + t];
                unsigned bb[2] = { f2tf(kb[0]), f2tf(kb[4]) };
                mma_tf32(sc[j], qf[s], bb);
            }
        }
#pragma unroll
        for (int j = 0; j < 8; j++)
#pragma unroll
            for (int e = 0; e < 4; e++) sc[j][e] *= 0.125f;   // 1/sqrt(64)

        // ---- Online softmax (rows g, g+8); p (tf32-rounded) back into sc
        float mx0 = -1e30f, mx1 = -1e30f;
#pragma unroll
        for (int j = 0; j < 8; j++) {
            mx0 = fmaxf(mx0, fmaxf(sc[j][0], sc[j][1]));
            mx1 = fmaxf(mx1, fmaxf(sc[j][2], sc[j][3]));
        }
        mx0 = fmaxf(mx0, __shfl_xor_sync(0xffffffffu, mx0, 1));
        mx0 = fmaxf(mx0, __shfl_xor_sync(0xffffffffu, mx0, 2));
        mx1 = fmaxf(mx1, __shfl_xor_sync(0xffffffffu, mx1, 1));
        mx1 = fmaxf(mx1, __shfl_xor_sync(0xffffffffu, mx1, 2));

        float mn0 = fmaxf(m0, mx0);
        float mn1 = fmaxf(m1, mx1);
        float corr0 = __expf(m0 - mn0);
        float corr1 = __expf(m1 - mn1);

        float rs0 = 0.0f, rs1 = 0.0f;
#pragma unroll
        for (int j = 0; j < 8; j++) {
            float p0 = f2tff(__expf(sc[j][0] - mn0));
            float p1 = f2tff(__expf(sc[j][1] - mn0));
            float p2 = f2tff(__expf(sc[j][2] - mn1));
            float p3 = f2tff(__expf(sc[j][3] - mn1));
            rs0 += p0 + p1;
            rs1 += p2 + p3;
            sc[j][0] = p0; sc[j][1] = p1; sc[j][2] = p2; sc[j][3] = p3;
        }
        rs0 += __shfl_xor_sync(0xffffffffu, rs0, 1);
        rs0 += __shfl_xor_sync(0xffffffffu, rs0, 2);
        rs1 += __shfl_xor_sync(0xffffffffu, rs1, 1);
        rs1 += __shfl_xor_sync(0xffffffffu, rs1, 2);

        l0 = l0 * corr0 + rs0;
        l1 = l1 * corr1 + rs1;
#pragma unroll
        for (int j = 0; j < 8; j++) {
            o[j][0] *= corr0; o[j][1] *= corr0;
            o[j][2] *= corr1; o[j][3] *= corr1;
        }
        m0 = mn0; m1 = mn1;

        // ---- O += P V : P C-frag (keys 2t,2t+1) -> A-frag (keys t,t+4) via shfl
#pragma unroll
        for (int kk = 0; kk < 8; kk++) {
            float v00 = __shfl_sync(0xffffffffu, sc[kk][0], s0lane);
            float v01 = __shfl_sync(0xffffffffu, sc[kk][1], s0lane);
            float v02 = __shfl_sync(0xffffffffu, sc[kk][2], s0lane);
            float v03 = __shfl_sync(0xffffffffu, sc[kk][3], s0lane);
            float v10 = __shfl_sync(0xffffffffu, sc[kk][0], s1lane);
            float v11 = __shfl_sync(0xffffffffu, sc[kk][1], s1lane);
            float v12 = __shfl_sync(0xffffffffu, sc[kk][2], s1lane);
            float v13 = __shfl_sync(0xffffffffu, sc[kk][3], s1lane);
            unsigned pf[4];
            pf[0] = __float_as_uint(odd ? v01 : v00);   // P[g   ][t]
            pf[1] = __float_as_uint(odd ? v03 : v02);   // P[g+8 ][t]
            pf[2] = __float_as_uint(odd ? v11 : v10);   // P[g   ][t+4]
            pf[3] = __float_as_uint(odd ? v13 : v12);   // P[g+8 ][t+4]
#pragma unroll
            for (int j2 = 0; j2 < 8; j2++) {
                const float* vb = &Vc[(kk * 8 + t) * VSTR + j2 * 8 + g];
                unsigned bb[2] = { f2tf(vb[0]), f2tf(vb[4 * VSTR]) };
                mma_tf32(o[j2], pf, bb);
            }
        }
        __syncthreads();   // readers done before this stage is overwritten
    }

    // ---- Normalize and write out ([b*t][h*64])
    float inv0 = 1.0f / l0;
    float inv1 = 1.0f / l1;
    size_t orow0 = (rowbase + qtile * 64 + wrow + g) * KDIM + colbase;
    size_t orow1 = orow0 + (size_t)8 * KDIM;
#pragma unroll
    for (int j = 0; j < 8; j++) {
        int col = 8 * j + 2 * t;
        *(float2*)&O[orow0 + col] = make_float2(o[j][0] * inv0, o[j][1] * inv0);
        *(float2*)&O[orow1 + col] = make_float2(o[j][2] * inv1, o[j][3] * inv1);
    }
}

// ---------------------------------------------------------------------------
// Launcher
// ---------------------------------------------------------------------------
extern "C" void kernel_launch(void* const* d_in, const int* in_sizes, int n_in,
                              void* d_out, int out_size)
{
    const float* x  = (const float*)d_in[0];
    const float* Wq = (const float*)d_in[1];
    const float* Wk = (const float*)d_in[2];
    const float* Wv = (const float*)d_in[3];
    const float* Wu = (const float*)d_in[4];
    const float* bu = (const float*)d_in[5];
    float* out = (float*)d_out;

    float *q, *k, *v, *a;
    cudaGetSymbolAddress((void**)&q, g_q);
    cudaGetSymbolAddress((void**)&k, g_k);
    cudaGetSymbolAddress((void**)&v, g_v);
    cudaGetSymbolAddress((void**)&a, g_a);

    const int gemm_smem = 4 * 128 * GS * (int)sizeof(float);   // 73728 B
    cudaFuncSetAttribute(gemm_tc<0>, cudaFuncAttributeMaxDynamicSharedMemorySize, gemm_smem);
    cudaFuncSetAttribute(gemm_tc<1>, cudaFuncAttributeMaxDynamicSharedMemorySize, gemm_smem);
    cudaFuncSetAttribute(gemm_tc<2>, cudaFuncAttributeMaxDynamicSharedMemorySize, gemm_smem);

    dim3 ggrid(KDIM / 128, ROWS / 128);  // (8, 64)

    // QKV projections; RoPE fused into Q/K epilogues
    gemm_tc<1><<<ggrid, 256, gemm_smem>>>(x, Wq, nullptr, q, ROWS, KDIM, KDIM);
    gemm_tc<1><<<ggrid, 256, gemm_smem>>>(x, Wk, nullptr, k, ROWS, KDIM, KDIM);
    gemm_tc<0><<<ggrid, 256, gemm_smem>>>(x, Wv, nullptr, v, ROWS, KDIM, KDIM);

    // Attention
    const int attn_smem = 2 * SSZ * (int)sizeof(float);        // 71680 B
    cudaFuncSetAttribute(attn_tc, cudaFuncAttributeMaxDynamicSharedMemorySize, attn_smem);
    attn_tc<<<dim3(T_ / 64, B_ * HEADS), 128, attn_smem>>>(q, k, v, a);

    // Output projection + bias
    gemm_tc<2><<<ggrid, 256, gemm_smem>>>(a, Wu, bu, out, ROWS, KDIM, KDIM);
}

// round 5
// speedup vs baseline: 2.3074x; 1.0802x over previous
#include <cuda_runtime.h>
#include <cuda_bf16.h>
#include <math.h>

// Problem constants
#define B_      4
#define T_      2048
#define KDIM    1024
#define HEADS   16
#define HDIM    64
#define ROWS    (B_ * T_)          // 8192
#define HALF    (KDIM / 2)         // 512

// ---------------------------------------------------------------------------
// Scratch (device globals: allocation-free per harness rules)
// ---------------------------------------------------------------------------
__device__ float g_q[ROWS * KDIM];
__device__ float g_k[ROWS * KDIM];
__device__ float g_v[ROWS * KDIM];
__device__ float g_a[ROWS * KDIM];

// ---------------------------------------------------------------------------
// Helpers
// ---------------------------------------------------------------------------
__device__ __forceinline__ unsigned f2tf(float f) {
    unsigned u;
    asm("cvt.rna.tf32.f32 %0, %1;" : "=r"(u) : "f"(f));
    return u;
}
__device__ __forceinline__ float f2tff(float f) {
    return __uint_as_float(f2tf(f));
}

// mma.sync m16n8k8 tf32: D = A*B + D
// A frag: a0=(g,t) a1=(g+8,t) a2=(g,t+4) a3=(g+8,t+4)  [g=lane>>2, t=lane&3]
// B frag: b0=(k=t,n=g) b1=(k=t+4,n=g)
// C frag: c0=(g,2t) c1=(g,2t+1) c2=(g+8,2t) c3=(g+8,2t+1)
__device__ __forceinline__ void mma_tf32(float* c, const unsigned* a, const unsigned* b) {
    asm volatile(
        "mma.sync.aligned.m16n8k8.row.col.f32.tf32.tf32.f32 "
        "{%0,%1,%2,%3}, {%4,%5,%6,%7}, {%8,%9}, {%0,%1,%2,%3};\n"
        : "+f"(c[0]), "+f"(c[1]), "+f"(c[2]), "+f"(c[3])
        : "r"(a[0]), "r"(a[1]), "r"(a[2]), "r"(a[3]), "r"(b[0]), "r"(b[1]));
}

__device__ __forceinline__ void cp16(float* dst_smem, const float* src) {
    unsigned d = (unsigned)__cvta_generic_to_shared(dst_smem);
    asm volatile("cp.async.cg.shared.global [%0], [%1], 16;\n" :: "r"(d), "l"(src));
}
#define CP_COMMIT() asm volatile("cp.async.commit_group;\n" ::: "memory")
#define CP_WAIT0()  asm volatile("cp.async.wait_group 0;\n" ::: "memory")

// in-place tf32 conversion of a 16-float smem span (4x float4)
__device__ __forceinline__ void cvt16_inplace(float* p) {
#pragma unroll
    for (int i = 0; i < 4; i++) {
        float4 v = *(float4*)(p + 4 * i);
        v.x = f2tff(v.x); v.y = f2tff(v.y);
        v.z = f2tff(v.z); v.w = f2tff(v.w);
        *(float4*)(p + 4 * i) = v;
    }
}

// ---------------------------------------------------------------------------
// Tensor-core GEMM: C[m][n] = sum_k A[m][k]*B[n][k]   (C = A @ B^T)
// MODE: 0 = plain, 1 = RoPE epilogue (Q/K proj), 2 = +bias (output proj)
// 128x128x32 CTA tile, 256 threads = 8 warps (2m x 4n), warp tile 64x32.
// cp.async 2-stage pipeline; raw fp32 lands in smem, then converted to tf32
// IN PLACE once per chunk -> mma loops are pure LDS + MMA.
// Stride 36 (mod 32 = 4) -> fragment lanes hit banks 4g+t: conflict-free.
// ---------------------------------------------------------------------------
#define GS 36

template<int MODE>
__global__ __launch_bounds__(256, 2) void gemm_tc(
    const float* __restrict__ A, const float* __restrict__ B,
    const float* __restrict__ bias, float* __restrict__ C,
    int M, int N, int Kd)
{
    extern __shared__ float sm[];
    float* As = sm;                 // [2][128*GS]
    float* Bs = sm + 2 * 128 * GS;  // [2][128*GS]

    const int tid  = threadIdx.x;
    const int lane = tid & 31;
    const int warp = tid >> 5;
    const int g = lane >> 2;
    const int t = lane & 3;
    const int wm = warp >> 2;      // 0..1
    const int wn = warp & 3;       // 0..3
    const int bm = blockIdx.y * 128;
    const int bn = blockIdx.x * 128;

    float c[4][4][4];
#pragma unroll
    for (int i = 0; i < 4; i++)
#pragma unroll
        for (int j = 0; j < 4; j++)
#pragma unroll
            for (int e = 0; e < 4; e++) c[i][j][e] = 0.0f;

    const int lrow = tid >> 1;          // 0..127
    const int lcb  = (tid & 1) * 16;    // 0 or 16
    const float* Ap = A + (size_t)(bm + lrow) * Kd + lcb;
    const float* Bp = B + (size_t)(bn + lrow) * Kd + lcb;
    float* Asl = &As[lrow * GS + lcb];
    float* Bsl = &Bs[lrow * GS + lcb];

    // prologue: stage 0 <- k0=0
#pragma unroll
    for (int i = 0; i < 4; i++) {
        cp16(Asl + 4 * i, Ap + 4 * i);
        cp16(Bsl + 4 * i, Bp + 4 * i);
    }
    CP_COMMIT();

    const int a_base0 = (wm * 64 + g) * GS;
    const int b_base0 = (wn * 32 + g) * GS;

    for (int k0 = 0; k0 < Kd; k0 += 32) {
        const int st = (k0 >> 5) & 1;
        CP_WAIT0();
        __syncthreads();
        if (k0 + 32 < Kd) {
            const int stn = st ^ 1;
            float* Asd = Asl + stn * 128 * GS;
            float* Bsd = Bsl + stn * 128 * GS;
#pragma unroll
            for (int i = 0; i < 4; i++) {
                cp16(Asd + 4 * i, Ap + k0 + 32 + 4 * i);
                cp16(Bsd + 4 * i, Bp + k0 + 32 + 4 * i);
            }
        }
        CP_COMMIT();

        // convert current stage to tf32 in place (each thread its own span)
        cvt16_inplace(Asl + st * 128 * GS);
        cvt16_inplace(Bsl + st * 128 * GS);
        __syncthreads();

        const float* Ac = As + st * 128 * GS;
        const float* Bc = Bs + st * 128 * GS;
#pragma unroll
        for (int s = 0; s < 4; s++) {
            unsigned a[4][4], b[4][2];
            const int kc = 8 * s + t;
#pragma unroll
            for (int mt = 0; mt < 4; mt++) {
                const float* p = &Ac[a_base0 + mt * 16 * GS + kc];
                a[mt][0] = __float_as_uint(p[0]);
                a[mt][1] = __float_as_uint(p[8 * GS]);
                a[mt][2] = __float_as_uint(p[4]);
                a[mt][3] = __float_as_uint(p[8 * GS + 4]);
            }
#pragma unroll
            for (int nt = 0; nt < 4; nt++) {
                const float* p = &Bc[b_base0 + nt * 8 * GS + kc];
                b[nt][0] = __float_as_uint(p[0]);
                b[nt][1] = __float_as_uint(p[4]);
            }
#pragma unroll
            for (int mt = 0; mt < 4; mt++)
#pragma unroll
                for (int nt = 0; nt < 4; nt++)
                    mma_tf32(c[mt][nt], a[mt], b[nt]);
        }
    }

    // Epilogue
#pragma unroll
    for (int mt = 0; mt < 4; mt++) {
        int row = bm + wm * 64 + mt * 16 + g;
#pragma unroll
        for (int nt = 0; nt < 4; nt++) {
            int col = bn + wn * 32 + nt * 8 + 2 * t;   // even
            float v0x = c[mt][nt][0], v0y = c[mt][nt][1];
            float v1x = c[mt][nt][2], v1y = c[mt][nt][3];
            if (MODE == 1) {
                int j = col >> 1;
                float theta = powf(10000.0f, -(float)j * (1.0f / (float)HALF));
                int t0 = row & (T_ - 1);
                float s0, c0; sincosf((float)t0 * theta, &s0, &c0);
                float s1, c1; sincosf((float)(t0 + 8) * theta, &s1, &c1);
                float r0x = v0x * c0 - v0y * s0;
                float r0y = v0x * s0 + v0y * c0;
                float r1x = v1x * c1 - v1y * s1;
                float r1y = v1x * s1 + v1y * c1;
                v0x = r0x; v0y = r0y; v1x = r1x; v1y = r1y;
            } else if (MODE == 2) {
                float bx = bias[col], by = bias[col + 1];
                v0x += bx; v0y += by; v1x += bx; v1y += by;
            }
            *(float2*)&C[(size_t)row * N + col] = make_float2(v0x, v0y);
            *(float2*)&C[(size_t)(row + 8) * N + col] = make_float2(v1x, v1y);
        }
    }
}

// ---------------------------------------------------------------------------
// Flash attention, tf32 mma.  CTA = 128 q-rows x (batch*head), 8 warps.
// Warp w owns q-rows [w*16, w*16+16).  BN=64 keys/iter.
// Q: tf32-converted in smem (stride 68, banks 4g+t conflict-free),
//    fragments re-loaded per tile (keeps regs <= 128 -> 2 CTAs/SM).
// K stride 68, V stride 72 (banks 8t+g), cp.async 2-stage pipeline with
// in-place tf32 conversion per tile -> mma loops pure LDS + MMA.
// P redistributed C-frag -> A-frag via shfl (no smem round-trip).
// ---------------------------------------------------------------------------
#define QSTR 68
#define KSTR 68
#define VSTR 72
#define QSZ  (128 * QSTR)              // 8704 floats
#define SSZ  (64 * KSTR + 64 * VSTR)   // 8960 floats per stage

__global__ __launch_bounds__(256, 2) void attn_tc(
    const float* __restrict__ Q, const float* __restrict__ K,
    const float* __restrict__ V, float* __restrict__ O)
{
    extern __shared__ float sm[];
    float* Qs = sm;
    float* K0 = sm + QSZ;
    float* V0 = K0 + 64 * KSTR;
    float* K1 = sm + QSZ + SSZ;
    float* V1 = K1 + 64 * KSTR;

    const int tid  = threadIdx.x;
    const int lane = tid & 31;
    const int warp = tid >> 5;          // 0..7
    const int g = lane >> 2;
    const int t = lane & 3;
    const int wrow = warp * 16;

    const int qtile = blockIdx.x;       // 0..15
    const int bh = blockIdx.y;          // 0..63
    const int b = bh >> 4;
    const int h = bh & 15;
    const size_t rowbase = (size_t)b * T_;
    const int colbase = h * HDIM;

    // K/V loader: 4 threads per row, 16 floats each
    const int lrow4 = tid >> 2;         // 0..63
    const int lcb4  = (tid & 3) * 16;   // 0,16,32,48

    // ---- Stage Q tile [128 x 64] via cp.async, convert to tf32 in place
    {
        const int qrow = tid >> 1;          // 0..127
        const int qcb  = (tid & 1) * 32;
        const float* src = Q + (rowbase + qtile * 128 + qrow) * KDIM + colbase + qcb;
        float* dst = Qs + qrow * QSTR + qcb;
#pragma unroll
        for (int i = 0; i < 8; i++) cp16(dst + 4 * i, src + 4 * i);
        CP_COMMIT();
        CP_WAIT0();
        __syncthreads();
        cvt16_inplace(dst);
        cvt16_inplace(dst + 16);
    }

    // ---- prologue: tile 0 -> stage 0
    {
        const size_t gb = (rowbase + lrow4) * KDIM + colbase + lcb4;
        float* kd = K0 + lrow4 * KSTR + lcb4;
        float* vd = V0 + lrow4 * VSTR + lcb4;
#pragma unroll
        for (int i = 0; i < 4; i++) {
            cp16(kd + 4 * i, K + gb + 4 * i);
            cp16(vd + 4 * i, V + gb + 4 * i);
        }
        CP_COMMIT();
    }

    float m0 = -1e30f, m1 = -1e30f, l0 = 0.0f, l1 = 0.0f;
    float o[8][4];
#pragma unroll
    for (int j = 0; j < 8; j++)
#pragma unroll
        for (int e = 0; e < 4; e++) o[j][e] = 0.0f;

    const int s0lane = 4 * g + (t >> 1);
    const int s1lane = s0lane + 2;
    const bool odd = (t & 1);

    for (int kt = 0; kt < T_ / 64; kt++) {
        const int st = kt & 1;
        float* Kc = st ? K1 : K0;
        float* Vc = st ? V1 : V0;

        CP_WAIT0();
        __syncthreads();   // tile arrived; prev iter's smem reads done (Q cvt too)

        if (kt + 1 < T_ / 64) {
            const size_t gb = (rowbase + (kt + 1) * 64 + lrow4) * KDIM + colbase + lcb4;
            float* kd = (st ? K0 : K1) + lrow4 * KSTR + lcb4;
            float* vd = (st ? V0 : V1) + lrow4 * VSTR + lcb4;
#pragma unroll
            for (int i = 0; i < 4; i++) {
                cp16(kd + 4 * i, K + gb + 4 * i);
                cp16(vd + 4 * i, V + gb + 4 * i);
            }
        }
        CP_COMMIT();

        // convert current K/V tile to tf32 in place
        cvt16_inplace(Kc + lrow4 * KSTR + lcb4);
        cvt16_inplace(Vc + lrow4 * VSTR + lcb4);
        __syncthreads();

        // ---- S = Q K^T (warp tile 16 x 64), all operands pre-converted
        float sc[8][4];
#pragma unroll
        for (int j = 0; j < 8; j++)
#pragma unroll
            for (int e = 0; e < 4; e++) sc[j][e] = 0.0f;

#pragma unroll
        for (int s = 0; s < 8; s++) {
            const float* qp = &Qs[(wrow + g) * QSTR + 8 * s + t];
            unsigned qa[4];
            qa[0] = __float_as_uint(qp[0]);
            qa[1] = __float_as_uint(qp[8 * QSTR]);
            qa[2] = __float_as_uint(qp[4]);
            qa[3] = __float_as_uint(qp[8 * QSTR + 4]);
#pragma unroll
            for (int j = 0; j < 8; j++) {
                const float* kb = &Kc[(j * 8 + g) * KSTR + 8 * s + t];
                unsigned bb[2] = { __float_as_uint(kb[0]), __float_as_uint(kb[4]) };
                mma_tf32(sc[j], qa, bb);
            }
        }
#pragma unroll
        for (int j = 0; j < 8; j++)
#pragma unroll
            for (int e = 0; e < 4; e++) sc[j][e] *= 0.125f;   // 1/sqrt(64)

        // ---- Online softmax (rows g, g+8)
        float mx0 = -1e30f, mx1 = -1e30f;
#pragma unroll
        for (int j = 0; j < 8; j++) {
            mx0 = fmaxf(mx0, fmaxf(sc[j][0], sc[j][1]));
            mx1 = fmaxf(mx1, fmaxf(sc[j][2], sc[j][3]));
        }
        mx0 = fmaxf(mx0, __shfl_xor_sync(0xffffffffu, mx0, 1));
        mx0 = fmaxf(mx0, __shfl_xor_sync(0xffffffffu, mx0, 2));
        mx1 = fmaxf(mx1, __shfl_xor_sync(0xffffffffu, mx1, 1));
        mx1 = fmaxf(mx1, __shfl_xor_sync(0xffffffffu, mx1, 2));

        float mn0 = fmaxf(m0, mx0);
        float mn1 = fmaxf(m1, mx1);
        float corr0 = __expf(m0 - mn0);
        float corr1 = __expf(m1 - mn1);

        float rs0 = 0.0f, rs1 = 0.0f;
#pragma unroll
        for (int j = 0; j < 8; j++) {
            float p0 = f2tff(__expf(sc[j][0] - mn0));
            float p1 = f2tff(__expf(sc[j][1] - mn0));
            float p2 = f2tff(__expf(sc[j][2] - mn1));
            float p3 = f2tff(__expf(sc[j][3] - mn1));
            rs0 += p0 + p1;
            rs1 += p2 + p3;
            sc[j][0] = p0; sc[j][1] = p1; sc[j][2] = p2; sc[j][3] = p3;
        }
        rs0 += __shfl_xor_sync(0xffffffffu, rs0, 1);
        rs0 += __shfl_xor_sync(0xffffffffu, rs0, 2);
        rs1 += __shfl_xor_sync(0xffffffffu, rs1, 1);
        rs1 += __shfl_xor_sync(0xffffffffu, rs1, 2);

        l0 = l0 * corr0 + rs0;
        l1 = l1 * corr1 + rs1;
#pragma unroll
        for (int j = 0; j < 8; j++) {
            o[j][0] *= corr0; o[j][1] *= corr0;
            o[j][2] *= corr1; o[j][3] *= corr1;
        }
        m0 = mn0; m1 = mn1;

        // ---- O += P V : P C-frag (keys 2t,2t+1) -> A-frag (keys t,t+4) via shfl
#pragma unroll
        for (int kk = 0; kk < 8; kk++) {
            float v00 = __shfl_sync(0xffffffffu, sc[kk][0], s0lane);
            float v01 = __shfl_sync(0xffffffffu, sc[kk][1], s0lane);
            float v02 = __shfl_sync(0xffffffffu, sc[kk][2], s0lane);
            float v03 = __shfl_sync(0xffffffffu, sc[kk][3], s0lane);
            float v10 = __shfl_sync(0xffffffffu, sc[kk][0], s1lane);
            float v11 = __shfl_sync(0xffffffffu, sc[kk][1], s1lane);
            float v12 = __shfl_sync(0xffffffffu, sc[kk][2], s1lane);
            float v13 = __shfl_sync(0xffffffffu, sc[kk][3], s1lane);
            unsigned pf[4];
            pf[0] = __float_as_uint(odd ? v01 : v00);   // P[g   ][t]
            pf[1] = __float_as_uint(odd ? v03 : v02);   // P[g+8 ][t]
            pf[2] = __float_as_uint(odd ? v11 : v10);   // P[g   ][t+4]
            pf[3] = __float_as_uint(odd ? v13 : v12);   // P[g+8 ][t+4]
#pragma unroll
            for (int j2 = 0; j2 < 8; j2++) {
                const float* vb = &Vc[(kk * 8 + t) * VSTR + j2 * 8 + g];
                unsigned bb[2] = { __float_as_uint(vb[0]), __float_as_uint(vb[4 * VSTR]) };
                mma_tf32(o[j2], pf, bb);
            }
        }
    }

    // ---- Normalize and write out ([b*t][h*64])
    float inv0 = 1.0f / l0;
    float inv1 = 1.0f / l1;
    size_t orow0 = (rowbase + qtile * 128 + wrow + g) * KDIM + colbase;
    size_t orow1 = orow0 + (size_t)8 * KDIM;
#pragma unroll
    for (int j = 0; j < 8; j++) {
        int col = 8 * j + 2 * t;
        *(float2*)&O[orow0 + col] = make_float2(o[j][0] * inv0, o[j][1] * inv0);
        *(float2*)&O[orow1 + col] = make_float2(o[j][2] * inv1, o[j][3] * inv1);
    }
}

// ---------------------------------------------------------------------------
// Launcher
// ---------------------------------------------------------------------------
extern "C" void kernel_launch(void* const* d_in, const int* in_sizes, int n_in,
                              void* d_out, int out_size)
{
    const float* x  = (const float*)d_in[0];
    const float* Wq = (const float*)d_in[1];
    const float* Wk = (const float*)d_in[2];
    const float* Wv = (const float*)d_in[3];
    const float* Wu = (const float*)d_in[4];
    const float* bu = (const float*)d_in[5];
    float* out = (float*)d_out;

    float *q, *k, *v, *a;
    cudaGetSymbolAddress((void**)&q, g_q);
    cudaGetSymbolAddress((void**)&k, g_k);
    cudaGetSymbolAddress((void**)&v, g_v);
    cudaGetSymbolAddress((void**)&a, g_a);

    const int gemm_smem = 4 * 128 * GS * (int)sizeof(float);   // 73728 B
    cudaFuncSetAttribute(gemm_tc<0>, cudaFuncAttributeMaxDynamicSharedMemorySize, gemm_smem);
    cudaFuncSetAttribute(gemm_tc<1>, cudaFuncAttributeMaxDynamicSharedMemorySize, gemm_smem);
    cudaFuncSetAttribute(gemm_tc<2>, cudaFuncAttributeMaxDynamicSharedMemorySize, gemm_smem);

    dim3 ggrid(KDIM / 128, ROWS / 128);  // (8, 64)

    // QKV projections; RoPE fused into Q/K epilogues
    gemm_tc<1><<<ggrid, 256, gemm_smem>>>(x, Wq, nullptr, q, ROWS, KDIM, KDIM);
    gemm_tc<1><<<ggrid, 256, gemm_smem>>>(x, Wk, nullptr, k, ROWS, KDIM, KDIM);
    gemm_tc<0><<<ggrid, 256, gemm_smem>>>(x, Wv, nullptr, v, ROWS, KDIM, KDIM);

    // Attention: 128 q-rows per CTA, 8 warps
    const int attn_smem = (QSZ + 2 * SSZ) * (int)sizeof(float);  // 106496 B
    cudaFuncSetAttribute(attn_tc, cudaFuncAttributeMaxDynamicSharedMemorySize, attn_smem);
    attn_tc<<<dim3(T_ / 128, B_ * HEADS), 256, attn_smem>>>(q, k, v, a);

    // Output projection + bias
    gemm_tc<2><<<ggrid, 256, gemm_smem>>>(a, Wu, bu, out, ROWS, KDIM, KDIM);
}